// round 17
// baseline (speedup 1.0000x reference)
#include <cuda_runtime.h>

#define IMG_W 512
#define IMG_H 512
#define N_IMG 48            // 16 batch * 3 channels
#define HT 4                // output rows per block strip
#define N_STRIPS (IMG_H / HT)
#define NBLK (N_STRIPS * N_IMG)
#define SW 528              // smem columns: s = x+8; float4-aligned rows
#define NT 256              // 8 warps
#define SM_FLOATS (4 * HT * SW)
#define SMEM_BYTES ((SM_FLOATS + 8) * 4)

typedef unsigned long long u64;

// zero-initialized at module load; last block of each launch resets them,
// so every graph replay starts from zero (deterministic).
__device__ double g_acc;
__device__ unsigned int g_cnt;

// literal taps (horizontal scalar pass -> FFMA immediate form, rt_SMSP=1)
#define WG_INIT {0.00102838f, 0.00759876f, 0.03600077f, 0.10936069f, \
                 0.21300554f, 0.26601173f, 0.21300554f, 0.10936069f, \
                 0.03600077f, 0.00759876f, 0.00102838f}
// symmetric: only 6 distinct weights (k and 10-k share)
#define WH_INIT {0.00102838f, 0.00759876f, 0.03600077f, 0.10936069f, \
                 0.21300554f, 0.26601173f}

// ---- packed f32x2 helpers (sm_100+; no packing MOVs needed in this usage) ----
__device__ __forceinline__ u64 fma2(u64 a, u64 b, u64 c) {
    u64 d; asm("fma.rn.f32x2 %0, %1, %2, %3;" : "=l"(d) : "l"(a), "l"(b), "l"(c)); return d;
}
__device__ __forceinline__ u64 mul2(u64 a, u64 b) {
    u64 d; asm("mul.rn.f32x2 %0, %1, %2;" : "=l"(d) : "l"(a), "l"(b)); return d;
}
__device__ __forceinline__ u64 bc2(float f) {
    unsigned int b = __float_as_uint(f);
    return ((u64)b << 32) | b;
}

// ---- compile-time tap application: weight index ALWAYS a constant ----
template<int I, int R>
struct VStep {
    static __device__ __forceinline__ void run(u64 p, u64 t, u64 s2, u64 q,
                                               u64* mp, u64* mt, u64* ms, u64* mq,
                                               const u64* wq) {
        constexpr int K = I - R;
        if constexpr (K >= 0 && K < 11) {
            constexpr int M = (K < 6) ? K : (10 - K);
            mp[R] = fma2(wq[M], p,  mp[R]);
            mt[R] = fma2(wq[M], t,  mt[R]);
            ms[R] = fma2(wq[M], s2, ms[R]);
            mq[R] = fma2(wq[M], q,  mq[R]);
        }
        if constexpr (R + 1 < HT)
            VStep<I, R + 1>::run(p, t, s2, q, mp, mt, ms, mq, wq);
    }
};

template<int I>
struct VRow {
    static __device__ __forceinline__ void run(const float* __restrict__ P,
                                               const float* __restrict__ T,
                                               int row0, int x0, bool interior,
                                               u64* mp, u64* mt, u64* ms, u64* mq,
                                               const u64* wq) {
        u64 p, t;
        if (interior) {
            p = *(const u64*)(P + (row0 - 5 + I) * IMG_W + x0);   // aligned LDG.64
            t = *(const u64*)(T + (row0 - 5 + I) * IMG_W + x0);
        } else {
            const int row = row0 - 5 + I;
            const bool ok = (row >= 0) && (row < IMG_H);
            p = ok ? *(const u64*)(P + row * IMG_W + x0) : 0ull;
            t = ok ? *(const u64*)(T + row * IMG_W + x0) : 0ull;
        }
        const u64 s2 = fma2(t, t, mul2(p, p));   // p^2 + t^2
        const u64 q  = mul2(p, t);               // p*t
        VStep<I, 0>::run(p, t, s2, q, mp, mt, ms, mq, wq);
        if constexpr (I + 1 < HT + 10)
            VRow<I + 1>::run(P, T, row0, x0, interior, mp, mt, ms, mq, wq);
    }
};

__global__ void __launch_bounds__(NT, 4) ssim_fused(const float* __restrict__ pred,
                                                    const float* __restrict__ tgt,
                                                    float* __restrict__ out) {
    extern __shared__ float sm[];
    float* wsum = sm + SM_FLOATS;
    const float wg[11] = WG_INIT;
    const float wh[6]  = WH_INIT;
    u64 wq[6];
    #pragma unroll
    for (int m = 0; m < 6; m++) wq[m] = bc2(wh[m]);

    const int img  = blockIdx.y;
    const int row0 = blockIdx.x * HT;
    const float* P = pred + (size_t)img * (IMG_W * IMG_H);
    const float* T = tgt  + (size_t)img * (IMG_W * IMG_H);
    const bool interior = (row0 >= 5) && (row0 + HT + 5 <= IMG_H);

    // ---- Vertical pass: f32x2 streaming accumulators, column pairs ----
    for (int i2 = threadIdx.x; i2 < SW / 2; i2 += NT) {
        const int x0 = 2 * i2 - 8;            // even; pair never straddles edge
        if (x0 < 0 || x0 >= IMG_W) {
            #pragma unroll
            for (int r = 0; r < HT; r++) {
                ((u64*)(sm + (0 * HT + r) * SW))[i2] = 0ull;
                ((u64*)(sm + (1 * HT + r) * SW))[i2] = 0ull;
                ((u64*)(sm + (2 * HT + r) * SW))[i2] = 0ull;
                ((u64*)(sm + (3 * HT + r) * SW))[i2] = 0ull;
            }
            continue;
        }
        u64 mp[HT], mt[HT], ms[HT], mq[HT];
        #pragma unroll
        for (int r = 0; r < HT; r++) { mp[r] = 0ull; mt[r] = 0ull; ms[r] = 0ull; mq[r] = 0ull; }

        VRow<0>::run(P, T, row0, x0, interior, mp, mt, ms, mq, wq);

        #pragma unroll
        for (int r = 0; r < HT; r++) {
            ((u64*)(sm + (0 * HT + r) * SW))[i2] = mp[r];
            ((u64*)(sm + (1 * HT + r) * SW))[i2] = mt[r];
            ((u64*)(sm + (2 * HT + r) * SW))[i2] = ms[r];
            ((u64*)(sm + (3 * HT + r) * SW))[i2] = mq[r];
        }
    }
    __syncthreads();

    // ---- Horizontal pass: 4-wide quads (lane-contiguous => conflict-free) ----
    const float C1 = 1e-4f, C2 = 9e-4f;
    float acc = 0.f;
    #pragma unroll 1
    for (int task = threadIdx.x; task < HT * (IMG_W / 4); task += NT) {  // 512
        const int r = task >> 7;       // row within strip
        const int q = task & 127;      // quad: outputs x0 = 4q .. 4q+3
        float h[4][4];
        #pragma unroll
        for (int ch = 0; ch < 4; ch++) {
            const float4* rowp = (const float4*)(sm + (ch * HT + r) * SW);
            float v[20];
            #pragma unroll
            for (int b = 0; b < 5; b++) {
                float4 f = rowp[q + b];   // s = 4q..4q+19 covers taps [4q+3, 4q+16]
                v[4 * b + 0] = f.x; v[4 * b + 1] = f.y;
                v[4 * b + 2] = f.z; v[4 * b + 3] = f.w;
            }
            #pragma unroll
            for (int j = 0; j < 4; j++) {
                float a = 0.f;
                #pragma unroll
                for (int k = 0; k < 11; k++) a = fmaf(wg[k], v[3 + j + k], a);
                h[ch][j] = a;
            }
        }
        #pragma unroll
        for (int j = 0; j < 4; j++) {
            float mx  = h[0][j], my = h[1][j];
            float mx2 = mx * mx, my2 = my * my, mxy = mx * my;
            float sgs  = h[2][j] - mx2 - my2;   // sg_x + sg_y
            float sgxy = h[3][j] - mxy;
            float num = (2.f * mxy + C1) * (2.f * sgxy + C2);
            float den = (mx2 + my2 + C1) * (sgs + C2);
            acc += __fdividef(num, den);
        }
    }

    // -------- block reduction + last-block finalize --------
    #pragma unroll
    for (int off = 16; off; off >>= 1)
        acc += __shfl_down_sync(0xffffffffu, acc, off);
    if ((threadIdx.x & 31) == 0) wsum[threadIdx.x >> 5] = acc;
    __syncthreads();

    if (threadIdx.x == 0) {
        float s = 0.f;
        #pragma unroll
        for (int i = 0; i < NT / 32; i++) s += wsum[i];
        atomicAdd(&g_acc, (double)s);
        __threadfence();
        unsigned int t = atomicAdd(&g_cnt, 1u);
        if (t == NBLK - 1) {
            double tot = atomicAdd(&g_acc, 0.0);   // coherent read (returns old)
            out[0] = 1.0f - (float)(tot / ((double)N_IMG * IMG_W * IMG_H));
            g_acc = 0.0;    // reset for next graph replay
            g_cnt = 0u;
        }
    }
}

extern "C" void kernel_launch(void* const* d_in, const int* in_sizes, int n_in,
                              void* d_out, int out_size) {
    const float* pred = (const float*)d_in[0];
    const float* tgt  = (const float*)d_in[1];

    cudaFuncSetAttribute(ssim_fused, cudaFuncAttributeMaxDynamicSharedMemorySize,
                         SMEM_BYTES);

    dim3 grid(N_STRIPS, N_IMG);
    ssim_fused<<<grid, NT, SMEM_BYTES>>>(pred, tgt, (float*)d_out);
}